// round 15
// baseline (speedup 1.0000x reference)
#include <cuda_runtime.h>
#include <cstdint>

#define NC      6
#define NWARPS  8
#define TPB     256
#define NCTAS   5
#define NBLOCKS (148 * NCTAS)   // 740
#define NVALS   13              // ht[6], hp[6], dsum
#define NSTAGE  3               // per-warp cp.async pipeline depth

// Per-block partials, [val][block]; fully overwritten each launch.
__device__ unsigned int g_part[NVALS][NBLOCKS];
__device__ unsigned int g_ticket;   // last-block-done counter; reset by last block

__device__ __forceinline__ void cp_async16(uint32_t dst, const void* src) {
    asm volatile("cp.async.cg.shared.global [%0], [%1], 16;" :: "r"(dst), "l"(src));
}
__device__ __forceinline__ void cp_commit() {
    asm volatile("cp.async.commit_group;" ::: "memory");
}
template <int N>
__device__ __forceinline__ void cp_wait() {
    asm volatile("cp.async.wait_group %0;" :: "n"(N) : "memory");
}

__device__ __forceinline__ void process2(
    float4 f0, float4 f1, float4 f2, int2 t2,
    unsigned long long& ht_pack, unsigned long long& hp_pack, unsigned int& dsum)
{
    float v[12];
    v[0]=f0.x; v[1]=f0.y; v[2]=f0.z;  v[3]=f0.w;
    v[4]=f1.x; v[5]=f1.y; v[6]=f1.z;  v[7]=f1.w;
    v[8]=f2.x; v[9]=f2.y; v[10]=f2.z; v[11]=f2.w;

    int tt[2];
    tt[0] = t2.x; tt[1] = t2.y;

    #pragma unroll
    for (int r = 0; r < 2; r++) {
        const int base = r * 6;
        float bv = v[base];
        int   bi = 0;
        #pragma unroll
        for (int c = 1; c < 6; c++) {
            // strict > keeps FIRST max, matching jnp.argmax tie-break
            if (v[base + c] > bv) { bv = v[base + c]; bi = c; }
        }
        const int t = tt[r];
        const int d = t - bi;
        dsum    += (unsigned)(d * d);
        ht_pack += 1ull << (t  * 10);
        hp_pack += 1ull << (bi * 10);
    }
}

__global__ void __launch_bounds__(TPB, NCTAS) kappa_fused_kernel(
    const float* __restrict__ yp,
    const int* __restrict__ yt,     // y_true is int32 (JAX x64-demotion)
    int n,
    float* __restrict__ out)
{
    // Per-warp, per-stage chunk buffers: 96 float4 = 64 rows = 1536 B.
    __shared__ float4 sbuf[NWARPS][NSTAGE][96];   // 36 KB

    const int tid  = threadIdx.x;
    const int warp = tid >> 5;
    const int lane = tid & 31;

    // Register accumulators: packed 6x10-bit histograms + squared-diff sum.
    unsigned long long ht_pack = 0ull;
    unsigned long long hp_pack = 0ull;
    unsigned int dsum = 0u;

    const float4* yp4 = (const float4*)yp;
    const int2*   yt2 = (const int2*)yt;

    const int nchunks = n >> 6;                       // 64 rows per warp-chunk
    const int gw = blockIdx.x * NWARPS + warp;        // global warp id
    const int nw = gridDim.x * NWARPS;                // total warps

    // Prologue: queue NSTAGE chunks via fire-and-forget cp.async (no registers,
    // no scoreboard stall). Always commit (empty groups keep counts uniform).
    #pragma unroll
    for (int s = 0; s < NSTAGE; s++) {
        const int c = gw + s * nw;
        if (c < nchunks) {
            const float4* p = yp4 + (size_t)c * 96;
            const uint32_t d =
                (uint32_t)__cvta_generic_to_shared(&sbuf[warp][s][lane]);
            cp_async16(d,        p + lane);
            cp_async16(d +  512, p + 32 + lane);
            cp_async16(d + 1024, p + 64 + lane);
        }
        cp_commit();
    }

    // Labels: depth-1 register prefetch (coalesced LDG.64, cheap).
    int2 tn;
    if (gw < nchunks) tn = __ldcg(yt2 + (size_t)gw * 32 + lane);

    for (int k = 0; ; k++) {
        const int c = gw + k * nw;
        if (c >= nchunks) break;
        const int slot = k % NSTAGE;

        cp_wait<NSTAGE - 1>();   // chunk k's group complete (per thread)
        __syncwarp();            // all lanes' data landed

        // Thread-major readback: float4 3*lane..3*lane+2 (stride-3: each
        // 8-lane phase tiles all 32 banks exactly once -> conflict-free).
        float4 f0 = sbuf[warp][slot][3 * lane + 0];
        float4 f1 = sbuf[warp][slot][3 * lane + 1];
        float4 f2 = sbuf[warp][slot][3 * lane + 2];

        const int2 tcur = tn;
        const int cn1 = c + nw;
        if (cn1 < nchunks) tn = __ldcg(yt2 + (size_t)cn1 * 32 + lane);

        process2(f0, f1, f2, tcur, ht_pack, hp_pack, dsum);

        __syncwarp();            // all lanes done reading slot before refill

        // Refill slot with chunk k + NSTAGE.
        const int cf = c + NSTAGE * nw;
        if (cf < nchunks) {
            const float4* p = yp4 + (size_t)cf * 96;
            const uint32_t d =
                (uint32_t)__cvta_generic_to_shared(&sbuf[warp][slot][lane]);
            cp_async16(d,        p + lane);
            cp_async16(d +  512, p + 32 + lane);
            cp_async16(d + 1024, p + 64 + lane);
        }
        cp_commit();
    }
    cp_wait<0>();

    // Tail rows (n % 64): block 0, scalar per thread.
    if (blockIdx.x == 0) {
        const int tbase = nchunks << 6;
        for (int r = tbase + tid; r < n; r += TPB) {
            const float* row = yp + (size_t)r * 6;
            float bv = row[0];
            int   bi = 0;
            #pragma unroll
            for (int cc = 1; cc < 6; cc++) {
                float x = row[cc];
                if (x > bv) { bv = x; bi = cc; }
            }
            const int t = yt[r];
            const int d = t - bi;
            dsum    += (unsigned)(d * d);
            ht_pack += 1ull << (t  * 10);
            hp_pack += 1ull << (bi * 10);
        }
    }

    // Unpack to 13 u32 and warp shuffle-reduce.
    unsigned int vals[NVALS];
    #pragma unroll
    for (int cc = 0; cc < NC; cc++) {
        vals[cc]      = (unsigned int)((ht_pack >> (cc * 10)) & 0x3FFu);
        vals[NC + cc] = (unsigned int)((hp_pack >> (cc * 10)) & 0x3FFu);
    }
    vals[12] = dsum;

    #pragma unroll
    for (int k = 0; k < NVALS; k++) {
        unsigned int s = vals[k];
        #pragma unroll
        for (int o = 16; o; o >>= 1)
            s += __shfl_xor_sync(0xffffffffu, s, o);
        vals[k] = s;
    }

    // Block merge via shared: lane 0 of each warp deposits its 13 sums.
    __shared__ unsigned int s_w[NWARPS][NVALS];
    if (lane == 0) {
        #pragma unroll
        for (int k = 0; k < NVALS; k++) s_w[warp][k] = vals[k];
    }
    __syncthreads();
    if (tid < NVALS) {
        unsigned int s = 0;
        #pragma unroll
        for (int w = 0; w < NWARPS; w++) s += s_w[w][tid];
        g_part[tid][blockIdx.x] = s;
    }
    __threadfence();   // release partials
    __syncthreads();

    // Last-block-done: final reduce + kappa.
    __shared__ unsigned int s_last;
    __shared__ unsigned int s_acc[NVALS];
    if (tid == 0)
        s_last = (atomicAdd(&g_ticket, 1u) == (unsigned)(gridDim.x - 1)) ? 1u : 0u;
    __syncthreads();
    if (!s_last) return;

    __threadfence();   // acquire: all blocks' partials visible

    if (tid < NVALS) s_acc[tid] = 0u;
    __syncthreads();

    // 13 values x 19 slices = 247 active threads.
    {
        const int k     = tid % NVALS;
        const int slice = tid / NVALS;
        if (slice < 19) {
            volatile const unsigned int* row = &g_part[k][0];
            unsigned int s = 0;
            for (int b = slice; b < NBLOCKS; b += 19) s += row[b];
            atomicAdd(&s_acc[k], s);
        }
    }
    __syncthreads();

    if (tid == 0) {
        double ht[NC], hp[NC];
        #pragma unroll
        for (int cc = 0; cc < NC; cc++) {
            ht[cc] = (double)s_acc[cc];
            hp[cc] = (double)s_acc[NC + cc];
        }
        const double num = (double)s_acc[12];   // sum W*conf (unnormalized)
        double den = 0.0;
        #pragma unroll
        for (int i = 0; i < NC; i++)
            #pragma unroll
            for (int j = 0; j < NC; j++)
                den += (double)((i - j) * (i - j)) * ht[i] * hp[j];
        const double N = (double)n;
        out[0] = (float)(1.0 - (num * N) / den);
        g_ticket = 0u;   // reset for next graph replay (deterministic)
    }
}

extern "C" void kernel_launch(void* const* d_in, const int* in_sizes, int n_in,
                              void* d_out, int out_size) {
    const float* yp  = (const float*)d_in[0];
    const int*   yt  = (const int*)d_in[1];
    float*       out = (float*)d_out;
    const int n = in_sizes[1];   // number of rows (y_true element count)

    kappa_fused_kernel<<<NBLOCKS, TPB>>>(yp, yt, n, out);
}

// round 16
// speedup vs baseline: 1.1450x; 1.1450x over previous
#include <cuda_runtime.h>

#define NC      6
#define NWARPS  8
#define TPB     256
#define NBLOCKS 592    // 148 SMs * 4 (4 CTAs/SM, 64-reg budget)
#define NVALS   13     // ht[6], hp[6], dsum

// Per-block partials, [val][block]; fully overwritten each launch.
__device__ unsigned int g_part[NVALS][NBLOCKS];
__device__ unsigned int g_ticket;   // last-block-done counter; reset by last block

__device__ __forceinline__ void process2(
    float4 f0, float4 f1, float4 f2, int2 t2,
    unsigned long long& ht_pack, unsigned long long& hp_pack, unsigned int& dsum)
{
    float v[12];
    v[0]=f0.x; v[1]=f0.y; v[2]=f0.z;  v[3]=f0.w;
    v[4]=f1.x; v[5]=f1.y; v[6]=f1.z;  v[7]=f1.w;
    v[8]=f2.x; v[9]=f2.y; v[10]=f2.z; v[11]=f2.w;

    int tt[2];
    tt[0] = t2.x; tt[1] = t2.y;

    #pragma unroll
    for (int r = 0; r < 2; r++) {
        const int base = r * 6;
        float bv = v[base];
        int   bi = 0;
        #pragma unroll
        for (int c = 1; c < 6; c++) {
            // strict > keeps FIRST max, matching jnp.argmax tie-break
            if (v[base + c] > bv) { bv = v[base + c]; bi = c; }
        }
        const int t = tt[r];
        const int d = t - bi;
        dsum    += (unsigned)(d * d);
        ht_pack += 1ull << (t  * 10);
        hp_pack += 1ull << (bi * 10);
    }
}

__global__ void __launch_bounds__(TPB, 4) kappa_fused_kernel(
    const float* __restrict__ yp,
    const int* __restrict__ yt,     // y_true is int32 (JAX x64-demotion)
    int n,
    float* __restrict__ out)
{
    // Per-warp transpose buffer: 96 float4 = one 64-row chunk (serially reused).
    __shared__ float4 xbuf[NWARPS][96];   // 12 KB

    const int tid  = threadIdx.x;
    const int warp = tid >> 5;
    const int lane = tid & 31;

    // Register accumulators: packed 6x10-bit histograms + squared-diff sum.
    unsigned long long ht_pack = 0ull;
    unsigned long long hp_pack = 0ull;
    unsigned int dsum = 0u;

    const float4* yp4 = (const float4*)yp;
    const int2*   yt2 = (const int2*)yt;

    const int nchunks = n >> 6;                       // 64 rows per warp-chunk
    const int gw = blockIdx.x * NWARPS + warp;        // global warp id
    const int nw = gridDim.x * NWARPS;                // total warps

    // Depth-2 register pipeline over warp-coalesced chunks:
    // slots A and B each hold one chunk (3 lane-contiguous float4 + labels).
    // Chunk k+2's LDG issues at iteration k -> ~2 iterations of latency slack;
    // 3.6KB in flight per warp, ~115KB/SM at 32 warps.
    float4 a0, a1, a2; int2 at;
    float4 b0, b1, b2; int2 bt;
    bool ha = (gw < nchunks);
    bool hb = (gw + nw < nchunks);
    if (ha) {
        const float4* p = yp4 + (size_t)gw * 96;
        a0 = __ldcg(p + lane);
        a1 = __ldcg(p + 32 + lane);
        a2 = __ldcg(p + 64 + lane);
        at = __ldcg(yt2 + (size_t)gw * 32 + lane);
    }
    if (hb) {
        const float4* p = yp4 + (size_t)(gw + nw) * 96;
        b0 = __ldcg(p + lane);
        b1 = __ldcg(p + 32 + lane);
        b2 = __ldcg(p + 64 + lane);
        bt = __ldcg(yt2 + (size_t)(gw + nw) * 32 + lane);
    }
    long long cnext = (long long)gw + 2LL * nw;   // next chunk index to fetch

    while (ha) {
        // ---- consume slot A ----
        {
            xbuf[warp][lane]      = a0;
            xbuf[warp][lane + 32] = a1;
            xbuf[warp][lane + 64] = a2;
            const int2 tcur = at;

            ha = (cnext < nchunks);
            if (ha) {   // refill A with chunk cnext (depth 2)
                const float4* p = yp4 + (size_t)cnext * 96;
                a0 = __ldcg(p + lane);
                a1 = __ldcg(p + 32 + lane);
                a2 = __ldcg(p + 64 + lane);
                at = __ldcg(yt2 + (size_t)cnext * 32 + lane);
            }
            cnext += nw;

            __syncwarp();
            float4 f0 = xbuf[warp][3 * lane + 0];   // stride-3: conflict-free
            float4 f1 = xbuf[warp][3 * lane + 1];
            float4 f2 = xbuf[warp][3 * lane + 2];
            __syncwarp();

            process2(f0, f1, f2, tcur, ht_pack, hp_pack, dsum);
        }

        if (!hb) break;

        // ---- consume slot B ----
        {
            xbuf[warp][lane]      = b0;
            xbuf[warp][lane + 32] = b1;
            xbuf[warp][lane + 64] = b2;
            const int2 tcur = bt;

            hb = (cnext < nchunks);
            if (hb) {   // refill B with chunk cnext (depth 2)
                const float4* p = yp4 + (size_t)cnext * 96;
                b0 = __ldcg(p + lane);
                b1 = __ldcg(p + 32 + lane);
                b2 = __ldcg(p + 64 + lane);
                bt = __ldcg(yt2 + (size_t)cnext * 32 + lane);
            }
            cnext += nw;

            __syncwarp();
            float4 f0 = xbuf[warp][3 * lane + 0];
            float4 f1 = xbuf[warp][3 * lane + 1];
            float4 f2 = xbuf[warp][3 * lane + 2];
            __syncwarp();

            process2(f0, f1, f2, tcur, ht_pack, hp_pack, dsum);
        }
    }

    // Tail rows (n % 64): block 0, scalar per thread.
    if (blockIdx.x == 0) {
        const int tbase = nchunks << 6;
        for (int r = tbase + tid; r < n; r += TPB) {
            const float* row = yp + (size_t)r * 6;
            float bv = row[0];
            int   bi = 0;
            #pragma unroll
            for (int cc = 1; cc < 6; cc++) {
                float x = row[cc];
                if (x > bv) { bv = x; bi = cc; }
            }
            const int t = yt[r];
            const int d = t - bi;
            dsum    += (unsigned)(d * d);
            ht_pack += 1ull << (t  * 10);
            hp_pack += 1ull << (bi * 10);
        }
    }

    // Unpack to 13 u32 and warp shuffle-reduce.
    unsigned int vals[NVALS];
    #pragma unroll
    for (int cc = 0; cc < NC; cc++) {
        vals[cc]      = (unsigned int)((ht_pack >> (cc * 10)) & 0x3FFu);
        vals[NC + cc] = (unsigned int)((hp_pack >> (cc * 10)) & 0x3FFu);
    }
    vals[12] = dsum;

    #pragma unroll
    for (int k = 0; k < NVALS; k++) {
        unsigned int s = vals[k];
        #pragma unroll
        for (int o = 16; o; o >>= 1)
            s += __shfl_xor_sync(0xffffffffu, s, o);
        vals[k] = s;
    }

    // Block merge via shared: lane 0 of each warp deposits its 13 sums.
    __shared__ unsigned int s_w[NWARPS][NVALS];
    if (lane == 0) {
        #pragma unroll
        for (int k = 0; k < NVALS; k++) s_w[warp][k] = vals[k];
    }
    __syncthreads();
    if (tid < NVALS) {
        unsigned int s = 0;
        #pragma unroll
        for (int w = 0; w < NWARPS; w++) s += s_w[w][tid];
        g_part[tid][blockIdx.x] = s;
    }
    __threadfence();   // release partials
    __syncthreads();

    // Last-block-done: final reduce + kappa.
    __shared__ unsigned int s_last;
    __shared__ unsigned int s_acc[NVALS];
    if (tid == 0)
        s_last = (atomicAdd(&g_ticket, 1u) == (unsigned)(gridDim.x - 1)) ? 1u : 0u;
    __syncthreads();
    if (!s_last) return;

    __threadfence();   // acquire: all blocks' partials visible

    if (tid < NVALS) s_acc[tid] = 0u;
    __syncthreads();

    // 13 values x 19 slices = 247 active threads.
    {
        const int k     = tid % NVALS;
        const int slice = tid / NVALS;
        if (slice < 19) {
            volatile const unsigned int* row = &g_part[k][0];
            unsigned int s = 0;
            for (int b = slice; b < NBLOCKS; b += 19) s += row[b];
            atomicAdd(&s_acc[k], s);
        }
    }
    __syncthreads();

    if (tid == 0) {
        double ht[NC], hp[NC];
        #pragma unroll
        for (int cc = 0; cc < NC; cc++) {
            ht[cc] = (double)s_acc[cc];
            hp[cc] = (double)s_acc[NC + cc];
        }
        const double num = (double)s_acc[12];   // sum W*conf (unnormalized)
        double den = 0.0;
        #pragma unroll
        for (int i = 0; i < NC; i++)
            #pragma unroll
            for (int j = 0; j < NC; j++)
                den += (double)((i - j) * (i - j)) * ht[i] * hp[j];
        const double N = (double)n;
        out[0] = (float)(1.0 - (num * N) / den);
        g_ticket = 0u;   // reset for next graph replay (deterministic)
    }
}

extern "C" void kernel_launch(void* const* d_in, const int* in_sizes, int n_in,
                              void* d_out, int out_size) {
    const float* yp  = (const float*)d_in[0];
    const int*   yt  = (const int*)d_in[1];
    float*       out = (float*)d_out;
    const int n = in_sizes[1];   // number of rows (y_true element count)

    kappa_fused_kernel<<<NBLOCKS, TPB>>>(yp, yt, n, out);
}

// round 17
// speedup vs baseline: 1.1509x; 1.0051x over previous
#include <cuda_runtime.h>

#define NC      6
#define NWARPS  8
#define TPB     256
#define NBLOCKS 592    // 148 SMs * 4 (4 CTAs/SM, 64-reg budget)
#define NVALS   13     // ht[6], hp[6], dsum

// Per-block partials, [val][block]; fully overwritten each launch.
__device__ unsigned int g_part[NVALS][NBLOCKS];
__device__ unsigned int g_ticket;   // last-block-done counter; reset by last block

__device__ __forceinline__ void process2(
    float4 f0, float4 f1, float4 f2, int2 t2,
    unsigned long long& ht_pack, unsigned long long& hp_pack, unsigned int& dsum)
{
    float v[12];
    v[0]=f0.x; v[1]=f0.y; v[2]=f0.z;  v[3]=f0.w;
    v[4]=f1.x; v[5]=f1.y; v[6]=f1.z;  v[7]=f1.w;
    v[8]=f2.x; v[9]=f2.y; v[10]=f2.z; v[11]=f2.w;

    int tt[2];
    tt[0] = t2.x; tt[1] = t2.y;

    #pragma unroll
    for (int r = 0; r < 2; r++) {
        const int base = r * 6;
        float bv = v[base];
        int   bi = 0;
        #pragma unroll
        for (int c = 1; c < 6; c++) {
            // strict > keeps FIRST max, matching jnp.argmax tie-break
            if (v[base + c] > bv) { bv = v[base + c]; bi = c; }
        }
        const int t = tt[r];
        const int d = t - bi;
        dsum    += (unsigned)(d * d);
        ht_pack += 1ull << (t  * 10);
        hp_pack += 1ull << (bi * 10);
    }
}

__global__ void __launch_bounds__(TPB, 4) kappa_fused_kernel(
    const float* __restrict__ yp,
    const int* __restrict__ yt,     // y_true is int32 (JAX x64-demotion)
    int n,
    float* __restrict__ out)
{
    // Per-warp transpose buffer: 192 float4 = one 128-row chunk.
    __shared__ float4 xbuf[NWARPS][192];   // 24 KB

    const int tid  = threadIdx.x;
    const int warp = tid >> 5;
    const int lane = tid & 31;

    // Register accumulators: packed 6x10-bit histograms + squared-diff sum.
    unsigned long long ht_pack = 0ull;
    unsigned long long hp_pack = 0ull;
    unsigned int dsum = 0u;

    const float4* yp4 = (const float4*)yp;
    const int2*   yt2 = (const int2*)yt;

    const int nchunks = n >> 7;                       // 128 rows per warp-chunk
    const int gw = blockIdx.x * NWARPS + warp;        // global warp id
    const int nw = gridDim.x * NWARPS;                // total warps

    int c = gw;
    bool have = (c < nchunks);

    // Warp-coalesced loads: 6 lane-contiguous LDG.128 + 2 LDG.64 per chunk
    // (3.6 KB/warp in flight through the whole consume phase at depth 1).
    float4 v0, v1, v2, v3, v4, v5; int2 ta, tb;
    if (have) {
        const float4* p = yp4 + (size_t)c * 192;
        v0 = __ldcg(p + lane);
        v1 = __ldcg(p + 32 + lane);
        v2 = __ldcg(p + 64 + lane);
        v3 = __ldcg(p + 96 + lane);
        v4 = __ldcg(p + 128 + lane);
        v5 = __ldcg(p + 160 + lane);
        ta = __ldcg(yt2 + (size_t)c * 64 + lane);        // rows 2*lane, 2*lane+1
        tb = __ldcg(yt2 + (size_t)c * 64 + 32 + lane);   // rows 64+2*lane, +1
    }

    while (have) {
        // Stage current chunk lane-major (conflict-free STS.128).
        xbuf[warp][lane]       = v0;
        xbuf[warp][lane +  32] = v1;
        xbuf[warp][lane +  64] = v2;
        xbuf[warp][lane +  96] = v3;
        xbuf[warp][lane + 128] = v4;
        xbuf[warp][lane + 160] = v5;
        const int2 tcurA = ta, tcurB = tb;

        // Prefetch next chunk while this one is consumed.
        const int  cn    = c + nw;
        const bool haven = (cn < nchunks);
        if (haven) {
            const float4* p = yp4 + (size_t)cn * 192;
            v0 = __ldcg(p + lane);
            v1 = __ldcg(p + 32 + lane);
            v2 = __ldcg(p + 64 + lane);
            v3 = __ldcg(p + 96 + lane);
            v4 = __ldcg(p + 128 + lane);
            v5 = __ldcg(p + 160 + lane);
            ta = __ldcg(yt2 + (size_t)cn * 64 + lane);
            tb = __ldcg(yt2 + (size_t)cn * 64 + 32 + lane);
        }

        __syncwarp();
        // Pass 1: rows 2*lane, 2*lane+1 (float4 3*lane..3*lane+2; stride-3:
        // each 8-lane phase tiles all 32 banks once -> conflict-free).
        {
            float4 f0 = xbuf[warp][3 * lane + 0];
            float4 f1 = xbuf[warp][3 * lane + 1];
            float4 f2 = xbuf[warp][3 * lane + 2];
            process2(f0, f1, f2, tcurA, ht_pack, hp_pack, dsum);
        }
        // Pass 2: rows 64+2*lane, 64+2*lane+1 (offset 96 float4).
        {
            float4 f0 = xbuf[warp][96 + 3 * lane + 0];
            float4 f1 = xbuf[warp][96 + 3 * lane + 1];
            float4 f2 = xbuf[warp][96 + 3 * lane + 2];
            process2(f0, f1, f2, tcurB, ht_pack, hp_pack, dsum);
        }
        __syncwarp();   // all lanes done reading before next iter's STS

        c = cn; have = haven;
    }

    // Tail rows (n % 128): block 0, scalar per thread.
    if (blockIdx.x == 0) {
        const int tbase = nchunks << 7;
        for (int r = tbase + tid; r < n; r += TPB) {
            const float* row = yp + (size_t)r * 6;
            float bv = row[0];
            int   bi = 0;
            #pragma unroll
            for (int cc = 1; cc < 6; cc++) {
                float x = row[cc];
                if (x > bv) { bv = x; bi = cc; }
            }
            const int t = yt[r];
            const int d = t - bi;
            dsum    += (unsigned)(d * d);
            ht_pack += 1ull << (t  * 10);
            hp_pack += 1ull << (bi * 10);
        }
    }

    // Unpack to 13 u32 and warp shuffle-reduce.
    unsigned int vals[NVALS];
    #pragma unroll
    for (int cc = 0; cc < NC; cc++) {
        vals[cc]      = (unsigned int)((ht_pack >> (cc * 10)) & 0x3FFu);
        vals[NC + cc] = (unsigned int)((hp_pack >> (cc * 10)) & 0x3FFu);
    }
    vals[12] = dsum;

    #pragma unroll
    for (int k = 0; k < NVALS; k++) {
        unsigned int s = vals[k];
        #pragma unroll
        for (int o = 16; o; o >>= 1)
            s += __shfl_xor_sync(0xffffffffu, s, o);
        vals[k] = s;
    }

    // Block merge via shared: lane 0 of each warp deposits its 13 sums.
    __shared__ unsigned int s_w[NWARPS][NVALS];
    if (lane == 0) {
        #pragma unroll
        for (int k = 0; k < NVALS; k++) s_w[warp][k] = vals[k];
    }
    __syncthreads();
    if (tid < NVALS) {
        unsigned int s = 0;
        #pragma unroll
        for (int w = 0; w < NWARPS; w++) s += s_w[w][tid];
        g_part[tid][blockIdx.x] = s;
    }
    __threadfence();   // release partials
    __syncthreads();

    // Last-block-done: final reduce + kappa.
    __shared__ unsigned int s_last;
    __shared__ unsigned int s_acc[NVALS];
    if (tid == 0)
        s_last = (atomicAdd(&g_ticket, 1u) == (unsigned)(gridDim.x - 1)) ? 1u : 0u;
    __syncthreads();
    if (!s_last) return;

    __threadfence();   // acquire: all blocks' partials visible

    if (tid < NVALS) s_acc[tid] = 0u;
    __syncthreads();

    // 13 values x 19 slices = 247 active threads.
    {
        const int k     = tid % NVALS;
        const int slice = tid / NVALS;
        if (slice < 19) {
            volatile const unsigned int* row = &g_part[k][0];
            unsigned int s = 0;
            for (int b = slice; b < NBLOCKS; b += 19) s += row[b];
            atomicAdd(&s_acc[k], s);
        }
    }
    __syncthreads();

    if (tid == 0) {
        double ht[NC], hp[NC];
        #pragma unroll
        for (int cc = 0; cc < NC; cc++) {
            ht[cc] = (double)s_acc[cc];
            hp[cc] = (double)s_acc[NC + cc];
        }
        const double num = (double)s_acc[12];   // sum W*conf (unnormalized)
        double den = 0.0;
        #pragma unroll
        for (int i = 0; i < NC; i++)
            #pragma unroll
            for (int j = 0; j < NC; j++)
                den += (double)((i - j) * (i - j)) * ht[i] * hp[j];
        const double N = (double)n;
        out[0] = (float)(1.0 - (num * N) / den);
        g_ticket = 0u;   // reset for next graph replay (deterministic)
    }
}

extern "C" void kernel_launch(void* const* d_in, const int* in_sizes, int n_in,
                              void* d_out, int out_size) {
    const float* yp  = (const float*)d_in[0];
    const int*   yt  = (const int*)d_in[1];
    float*       out = (float*)d_out;
    const int n = in_sizes[1];   // number of rows (y_true element count)

    kappa_fused_kernel<<<NBLOCKS, TPB>>>(yp, yt, n, out);
}